// round 4
// baseline (speedup 1.0000x reference)
#include <cuda_runtime.h>

// Problem constants (fixed by setup_inputs)
#define Bq 8
#define Cc 64
#define Hh 200
#define Ww 320
#define Nn 48
#define WD 80                       // W / STRIDE
static constexpr float FSTRIDE = 4.0f;   // pad_w / W = 1280 / 320
static constexpr float NEGV = -100000000.0f;

#define W2STRIDE 68                 // padded, float4-aligned, conflict-free
#define TILE 128                    // pixels per compute tile
#define TQ (TILE / 4)               // 32 float4 per row
#define NTHREADS 256

// Scratch (no allocation allowed): fused weights/bias per (b,n)
__device__ float g_W2[Bq * Nn * Cc];
__device__ float g_b2[Bq * Nn];

// ---- packed f32x2 helpers (FFMA2 path, PTX-only) ---------------------------
__device__ __forceinline__ unsigned long long pack_dup(float w) {
    unsigned long long r;
    asm("mov.b64 %0, {%1, %1};" : "=l"(r) : "f"(w));
    return r;
}
__device__ __forceinline__ unsigned long long pack2(float a, float b) {
    unsigned long long r;
    asm("mov.b64 %0, {%1, %2};" : "=l"(r) : "f"(a), "f"(b));
    return r;
}
__device__ __forceinline__ void fma2(unsigned long long& acc,
                                     unsigned long long a,
                                     unsigned long long b) {
    asm("fma.rn.f32x2 %0, %1, %2, %0;" : "+l"(acc) : "l"(a), "l"(b));
}
__device__ __forceinline__ float2 unpack2(unsigned long long v) {
    float2 r;
    asm("mov.b64 {%0, %1}, %2;" : "=f"(r.x), "=f"(r.y) : "l"(v));
    return r;
}

// ---------------------------------------------------------------------------
// Prep: per (b,n):
//   kfm[c] = mean_w kernel_feats[b,c,idx,w]
//   vk[o]  = bk[o] + Wk[o,:]·kfm ;  wgt=vk[0:64], bias=vk[64]
//   W2[c]  = wgt·Wf[:,c] ;  b2 = wgt·bf + bias
// ---------------------------------------------------------------------------
__global__ void prep_kernel(const float* __restrict__ kf,
                            const float* __restrict__ Wk,
                            const float* __restrict__ bk,
                            const float* __restrict__ Wf,
                            const float* __restrict__ bf,
                            const float* __restrict__ db,
                            float* __restrict__ centers_out) {
    const int bn  = blockIdx.x;
    const int b   = bn / Nn;
    const int tid = threadIdx.x;

    __shared__ float kfm[Cc];
    __shared__ float sW[Cc];
    __shared__ float sBias;

    const float y1 = db[bn * 4 + 1];
    const float y2 = db[bn * 4 + 3];
    const float yc = (y1 + y2) / (2.0f * FSTRIDE);
    const int  idx = (int)yc;
    if (tid == 0) centers_out[bn] = yc * FSTRIDE;

    {   // 2 threads per channel, 10 float4 each, combine via shfl
        const int c    = tid >> 1;
        const int half = tid & 1;
        const float4* p4 = (const float4*)(kf +
            (((size_t)b * Cc + c) * Hh + idx) * WD) + half * 10;
        float s = 0.0f;
        #pragma unroll
        for (int w = 0; w < 10; w++) {
            float4 v = p4[w];
            s += v.x + v.y + v.z + v.w;
        }
        s += __shfl_xor_sync(0xFFFFFFFFu, s, 1);
        if (half == 0) kfm[c] = s * (1.0f / (float)WD);
    }
    __syncthreads();

    if (tid <= Cc) {  // 65 rows of Wk
        float acc = bk[tid];
        const float4* wrow = (const float4*)(Wk + tid * Cc);
        #pragma unroll
        for (int c = 0; c < Cc / 4; c++) {
            float4 v = wrow[c];
            acc += v.x * kfm[c * 4 + 0] + v.y * kfm[c * 4 + 1]
                 + v.z * kfm[c * 4 + 2] + v.w * kfm[c * 4 + 3];
        }
        if (tid < Cc) sW[tid] = acc; else sBias = acc;
    }
    __syncthreads();

    if (tid < Cc) {
        float acc = 0.0f;
        #pragma unroll 16
        for (int o = 0; o < Cc; o++) acc += sW[o] * Wf[o * Cc + tid];
        g_W2[bn * Cc + tid] = acc;
    } else if (tid == Cc) {
        float acc = sBias;
        for (int o = 0; o < Cc; o++) acc += sW[o] * bf[o];
        g_b2[bn] = acc;
    }
}

// ---------------------------------------------------------------------------
// Main: logits[b,n,h,w] = W2[b,n,:]·feats[b,:,h,w] + b2[b,n], masked.
// Block = (b, h, 128-px tile), 256 threads = 8 warps.
// Warp grid: 4 px-quarters (32 px) x 2 n-halves (24 n).
// Within a warp: pg = lane&7 (4 px), ng = lane>>3 (n = wn*24 + ng + 4j, j<6).
// Pixel LDS.128: 8 distinct float4 in one 128B line -> 1 crossbar phase.
// Weight LDS.128: 4 distinct rows (64B)             -> 1 crossbar phase.
// ---------------------------------------------------------------------------
__global__ __launch_bounds__(NTHREADS)
void main_kernel(const float* __restrict__ feats,
                 const int* __restrict__ imshape,
                 float* __restrict__ logits) {
    const int b   = blockIdx.z;
    const int h   = blockIdx.y;
    const int w0  = blockIdx.x * TILE;       // 0, 128, 256
    const int tid = threadIdx.x;

    const int hlim = (int)((float)imshape[b * 2 + 1] / FSTRIDE);
    const int wlim = (int)((float)imshape[b * 2 + 0] / FSTRIDE);

    float* outbase = logits + ((size_t)b * Nn * Hh + h) * Ww + w0;
    const int tw = (w0 + TILE <= Ww) ? TILE : (Ww - w0);   // 128 or 64

    if (h >= hlim || w0 >= wlim) {
        // fully masked tile: fill 48 n x tw px
        const float4 fill = make_float4(NEGV, NEGV, NEGV, NEGV);
        const int quads = Nn * (tw / 4);                   // 1536 or 768
        for (int i = tid; i < quads; i += NTHREADS) {
            int n, q;
            if (tw == TILE) { n = i >> 5; q = i & 31; }
            else            { n = i >> 4; q = i & 15; }
            *(float4*)(outbase + (size_t)n * Hh * Ww + q * 4) = fill;
        }
        return;
    }

    __shared__ float W2s[Nn * W2STRIDE];   // 13.1 KB
    __shared__ float Fs[Cc * TILE];        // 32 KB  [c][px]

    // load fused weights (48 rows x 16 float4 = 768 float4)
    {
        const float4* w2g = (const float4*)(g_W2 + b * Nn * Cc);
        #pragma unroll
        for (int k = 0; k < 3; k++) {
            int i = tid + k * NTHREADS;
            int n = i >> 4, q = i & 15;
            *(float4*)&W2s[n * W2STRIDE + q * 4] = w2g[i];
        }
    }
    // load feats tile: 64 channels x 128 px (2048 float4)
    {
        const float4* src = (const float4*)(feats +
            (((size_t)b * Cc) * Hh + h) * Ww + w0);
        const int rowq = (Hh * Ww) / 4;    // float4 stride between channels
        #pragma unroll
        for (int k = 0; k < 8; k++) {
            int i = tid + k * NTHREADS;
            int c = i >> 5, q = i & 31;
            ((float4*)Fs)[i] = src[(size_t)c * rowq + q];
        }
    }
    __syncthreads();

    const int lane = tid & 31;
    const int wrp  = tid >> 5;     // 0..7
    const int wq   = wrp & 3;      // px quarter (32 px)
    const int wn   = wrp >> 2;     // n half (24 n)
    const int pg   = lane & 7;
    const int ng   = lane >> 3;    // n = wn*24 + ng + 4*j
    const int pbase = wq * 8 + pg;        // float4 index within row
    const int px0   = pbase * 4;
    const int nbase = wn * 24 + ng;

    // accumulators: 6 n-rows x 2 pixel-pairs
    unsigned long long acc[6][2];
    #pragma unroll
    for (int j = 0; j < 6; j++) {
        float b2v = g_b2[b * Nn + nbase + 4 * j];
        acc[j][0] = pack_dup(b2v);
        acc[j][1] = acc[j][0];
    }

    const float4* Fs4 = (const float4*)Fs;
    #pragma unroll 2
    for (int c4 = 0; c4 < Cc / 4; c4++) {
        unsigned long long fp[4][2];
        #pragma unroll
        for (int cc = 0; cc < 4; cc++) {
            float4 fv = Fs4[(c4 * 4 + cc) * TQ + pbase];
            fp[cc][0] = pack2(fv.x, fv.y);
            fp[cc][1] = pack2(fv.z, fv.w);
        }
        #pragma unroll
        for (int j = 0; j < 6; j++) {
            float4 w4 = *(const float4*)&W2s[(nbase + 4 * j) * W2STRIDE + c4 * 4];
            unsigned long long wp;
            wp = pack_dup(w4.x); fma2(acc[j][0], fp[0][0], wp); fma2(acc[j][1], fp[0][1], wp);
            wp = pack_dup(w4.y); fma2(acc[j][0], fp[1][0], wp); fma2(acc[j][1], fp[1][1], wp);
            wp = pack_dup(w4.z); fma2(acc[j][0], fp[2][0], wp); fma2(acc[j][1], fp[2][1], wp);
            wp = pack_dup(w4.w); fma2(acc[j][0], fp[3][0], wp); fma2(acc[j][1], fp[3][1], wp);
        }
    }

    const int nvalid = wlim - w0;   // > 0 on this path
    #pragma unroll
    for (int j = 0; j < 6; j++) {
        const int n = nbase + 4 * j;
        float2 lo = unpack2(acc[j][0]);
        float2 hi = unpack2(acc[j][1]);
        float4 v;
        v.x = (px0 + 0 < nvalid) ? lo.x : NEGV;
        v.y = (px0 + 1 < nvalid) ? lo.y : NEGV;
        v.z = (px0 + 2 < nvalid) ? hi.x : NEGV;
        v.w = (px0 + 3 < nvalid) ? hi.y : NEGV;
        *(float4*)(outbase + (size_t)n * Hh * Ww + px0) = v;
    }
}

extern "C" void kernel_launch(void* const* d_in, const int* in_sizes, int n_in,
                              void* d_out, int out_size) {
    const float* feats   = (const float*)d_in[0];
    const float* kf      = (const float*)d_in[1];
    const float* Wk      = (const float*)d_in[2];
    const float* bk      = (const float*)d_in[3];
    const float* Wf      = (const float*)d_in[4];
    const float* bf      = (const float*)d_in[5];
    const float* db      = (const float*)d_in[6];
    const int*   imshape = (const int*)d_in[7];

    float* logits  = (float*)d_out;
    float* centers = logits + (size_t)Bq * Nn * Hh * Ww;

    prep_kernel<<<Bq * Nn, 128>>>(kf, Wk, bk, Wf, bf, db, centers);
    main_kernel<<<dim3((Ww + TILE - 1) / TILE, Hh, Bq), NTHREADS>>>(feats, imshape, logits);
}

// round 5
// speedup vs baseline: 1.1714x; 1.1714x over previous
#include <cuda_runtime.h>

// Problem constants (fixed by setup_inputs)
#define Bq 8
#define Cc 64
#define Hh 200
#define Ww 320
#define Nn 48
#define WD 80                       // W / STRIDE
static constexpr float FSTRIDE = 4.0f;   // pad_w / W = 1280 / 320
static constexpr float NEGV = -100000000.0f;

#define W2STRIDE 68                 // padded, float4-aligned, conflict-free
#define TILE 64                     // pixels per tile (Ww % 64 == 0)
#define TQ (TILE / 4)               // 16 float4 per channel row
#define GROUP 4                     // h rows per block

// Scratch (no allocation allowed): fused weights/bias per (b,n)
__device__ float g_W2[Bq * Nn * Cc];
__device__ float g_b2[Bq * Nn];

// ---- packed f32x2 helpers (FFMA2 path, PTX-only) ---------------------------
__device__ __forceinline__ unsigned long long pack_dup(float w) {
    unsigned long long r;
    asm("mov.b64 %0, {%1, %1};" : "=l"(r) : "f"(w));
    return r;
}
__device__ __forceinline__ unsigned long long pack2(float a, float b) {
    unsigned long long r;
    asm("mov.b64 %0, {%1, %2};" : "=l"(r) : "f"(a), "f"(b));
    return r;
}
__device__ __forceinline__ void fma2(unsigned long long& acc,
                                     unsigned long long a,
                                     unsigned long long b) {
    asm("fma.rn.f32x2 %0, %1, %2, %0;" : "+l"(acc) : "l"(a), "l"(b));
}
__device__ __forceinline__ float2 unpack2(unsigned long long v) {
    float2 r;
    asm("mov.b64 {%0, %1}, %2;" : "=f"(r.x), "=f"(r.y) : "l"(v));
    return r;
}
// ---- cp.async helpers -------------------------------------------------------
__device__ __forceinline__ void cp_async16(void* smem_dst, const void* gmem_src) {
    unsigned s = (unsigned)__cvta_generic_to_shared(smem_dst);
    asm volatile("cp.async.cg.shared.global [%0], [%1], 16;\n" :: "r"(s), "l"(gmem_src));
}
__device__ __forceinline__ void cp_commit() {
    asm volatile("cp.async.commit_group;\n");
}
__device__ __forceinline__ void cp_wait1() {
    asm volatile("cp.async.wait_group 1;\n");
}

// ---------------------------------------------------------------------------
// Prep: per (b,n):
//   kfm[c] = mean_w kernel_feats[b,c,idx,w]
//   vk[o]  = bk[o] + Wk[o,:]·kfm ;  wgt=vk[0:64], bias=vk[64]
//   W2[c]  = wgt·Wf[:,c] ;  b2 = wgt·bf + bias
// ---------------------------------------------------------------------------
__global__ void prep_kernel(const float* __restrict__ kf,
                            const float* __restrict__ Wk,
                            const float* __restrict__ bk,
                            const float* __restrict__ Wf,
                            const float* __restrict__ bf,
                            const float* __restrict__ db,
                            float* __restrict__ centers_out) {
    const int bn  = blockIdx.x;
    const int b   = bn / Nn;
    const int tid = threadIdx.x;

    __shared__ float kfm[Cc];
    __shared__ float sW[Cc];
    __shared__ float sBias;

    const float y1 = db[bn * 4 + 1];
    const float y2 = db[bn * 4 + 3];
    const float yc = (y1 + y2) / (2.0f * FSTRIDE);
    const int  idx = (int)yc;
    if (tid == 0) centers_out[bn] = yc * FSTRIDE;

    {   // 2 threads per channel, 10 float4 each, combine via shfl
        const int c    = tid >> 1;
        const int half = tid & 1;
        const float4* p4 = (const float4*)(kf +
            (((size_t)b * Cc + c) * Hh + idx) * WD) + half * 10;
        float s = 0.0f;
        #pragma unroll
        for (int w = 0; w < 10; w++) {
            float4 v = p4[w];
            s += v.x + v.y + v.z + v.w;
        }
        s += __shfl_xor_sync(0xFFFFFFFFu, s, 1);
        if (half == 0) kfm[c] = s * (1.0f / (float)WD);
    }
    __syncthreads();

    if (tid <= Cc) {  // 65 rows of Wk
        float acc = bk[tid];
        const float4* wrow = (const float4*)(Wk + tid * Cc);
        #pragma unroll
        for (int c = 0; c < Cc / 4; c++) {
            float4 v = wrow[c];
            acc += v.x * kfm[c * 4 + 0] + v.y * kfm[c * 4 + 1]
                 + v.z * kfm[c * 4 + 2] + v.w * kfm[c * 4 + 3];
        }
        if (tid < Cc) sW[tid] = acc; else sBias = acc;
    }
    __syncthreads();

    if (tid < Cc) {
        float acc = 0.0f;
        #pragma unroll 16
        for (int o = 0; o < Cc; o++) acc += sW[o] * Wf[o * Cc + tid];
        g_W2[bn * Cc + tid] = acc;
    } else if (tid == Cc) {
        float acc = sBias;
        for (int o = 0; o < Cc; o++) acc += sW[o] * bf[o];
        g_b2[bn] = acc;
    }
}

// ---------------------------------------------------------------------------
// Main: logits[b,n,h,w] = W2[b,n,:]·feats[b,:,h,w] + b2[b,n], masked.
// Block = (b, 4-row h group, 64-px tile), 128 threads = 4 warps.
// Rows pipelined with cp.async double buffering; W2s loaded once per block.
// Warp: pg = lane&7 (4 px), ng = lane>>3 (4 n-rows); warps = 2 px-halves
//       x 2 n-halves. Pixel LDS.128 = 128B contiguous -> 1 phase;
//       weight LDS.128 = 4 rows x 16B -> 1 phase. 10 phases / 48 FMA2 per c4.
// ---------------------------------------------------------------------------
__global__ __launch_bounds__(128)
void main_kernel(const float* __restrict__ feats,
                 const int* __restrict__ imshape,
                 float* __restrict__ logits) {
    const int b   = blockIdx.z;
    const int h0  = blockIdx.y * GROUP;
    const int w0  = blockIdx.x * TILE;
    const int tid = threadIdx.x;

    const int hlim = (int)((float)imshape[b * 2 + 1] / FSTRIDE);
    const int wlim = (int)((float)imshape[b * 2 + 0] / FSTRIDE);

    const float4 fillv = make_float4(NEGV, NEGV, NEGV, NEGV);
    // number of rows in this group needing compute
    int nrows = (w0 < wlim) ? min(GROUP, max(0, hlim - h0)) : 0;

    // fill all masked rows of the group first (independent stores)
    for (int g = nrows; g < GROUP; g++) {
        float* ob = logits + ((size_t)b * Nn * Hh + (h0 + g)) * Ww + w0;
        #pragma unroll
        for (int k = 0; k < 6; k++) {
            int i = tid + k * 128;
            int n = i >> 4, q = i & 15;
            *(float4*)(ob + (size_t)n * Hh * Ww + q * 4) = fillv;
        }
    }
    if (nrows == 0) return;

    __shared__ float W2s[Nn * W2STRIDE];      // 13.1 KB
    __shared__ float Fs[2][Cc * TILE];        // 2 x 16 KB

    const float* rowsrc = feats + ((size_t)b * Cc * Hh + h0) * Ww + w0;
    const size_t chanstride = (size_t)Hh * Ww;

    // prefetch row 0 into buffer 0 (8 x 16B per thread)
    {
        const int c = tid >> 4, q = tid & 15;
        #pragma unroll
        for (int k = 0; k < 8; k++)
            cp_async16(&Fs[0][(c + k * 8) * TILE + q * 4],
                       rowsrc + (c + k * 8) * chanstride + q * 4);
    }
    cp_commit();

    // stage fused weights (once per block): 768 float4 / 128 thr = 6 each
    {
        const float4* w2g = (const float4*)(g_W2 + b * Nn * Cc);
        #pragma unroll
        for (int k = 0; k < 6; k++) {
            int i = tid + k * 128;
            int n = i >> 4, q = i & 15;
            *(float4*)&W2s[n * W2STRIDE + q * 4] = w2g[i];
        }
    }

    const int lane = tid & 31;
    const int wrp  = tid >> 5;
    const int wpx  = wrp & 1;      // px half (32 px)
    const int wn   = wrp >> 1;     // n half (24 n)
    const int pg   = lane & 7;
    const int ng   = lane >> 3;
    const int pbase = wpx * 8 + pg;        // float4 index within 16-wide row
    const int px0   = pbase * 4;
    const int nbase = wn * 24 + ng;        // n = nbase + 4*j, j<6

    unsigned long long b2p[6];
    #pragma unroll
    for (int j = 0; j < 6; j++)
        b2p[j] = pack_dup(g_b2[b * Nn + nbase + 4 * j]);

    const int nvalid = wlim - w0;   // > 0 here

    for (int g = 0; g < nrows; g++) {
        // prefetch next row into the other buffer
        if (g + 1 < nrows) {
            const int c = tid >> 4, q = tid & 15;
            const float* src = rowsrc + (size_t)(g + 1) * Ww;
            float* dst = Fs[(g + 1) & 1];
            #pragma unroll
            for (int k = 0; k < 8; k++)
                cp_async16(&dst[(c + k * 8) * TILE + q * 4],
                           src + (c + k * 8) * chanstride + q * 4);
        }
        cp_commit();
        cp_wait1();            // row g's data has arrived
        __syncthreads();       // visible to all warps (covers W2s on g==0)

        const float4* Fs4 = (const float4*)Fs[g & 1];

        unsigned long long acc[6][2];
        #pragma unroll
        for (int j = 0; j < 6; j++) { acc[j][0] = b2p[j]; acc[j][1] = b2p[j]; }

        #pragma unroll 2
        for (int c4 = 0; c4 < Cc / 4; c4++) {
            unsigned long long fp[4][2];
            #pragma unroll
            for (int cc = 0; cc < 4; cc++) {
                float4 fv = Fs4[(c4 * 4 + cc) * TQ + pbase];
                fp[cc][0] = pack2(fv.x, fv.y);
                fp[cc][1] = pack2(fv.z, fv.w);
            }
            #pragma unroll
            for (int j = 0; j < 6; j++) {
                float4 w4 = *(const float4*)&W2s[(nbase + 4 * j) * W2STRIDE + c4 * 4];
                unsigned long long wp;
                wp = pack_dup(w4.x); fma2(acc[j][0], fp[0][0], wp); fma2(acc[j][1], fp[0][1], wp);
                wp = pack_dup(w4.y); fma2(acc[j][0], fp[1][0], wp); fma2(acc[j][1], fp[1][1], wp);
                wp = pack_dup(w4.z); fma2(acc[j][0], fp[2][0], wp); fma2(acc[j][1], fp[2][1], wp);
                wp = pack_dup(w4.w); fma2(acc[j][0], fp[3][0], wp); fma2(acc[j][1], fp[3][1], wp);
            }
        }

        float* ob = logits + ((size_t)b * Nn * Hh + (h0 + g)) * Ww + w0;
        #pragma unroll
        for (int j = 0; j < 6; j++) {
            const int n = nbase + 4 * j;
            float2 lo = unpack2(acc[j][0]);
            float2 hi = unpack2(acc[j][1]);
            float4 v;
            v.x = (px0 + 0 < nvalid) ? lo.x : NEGV;
            v.y = (px0 + 1 < nvalid) ? lo.y : NEGV;
            v.z = (px0 + 2 < nvalid) ? hi.x : NEGV;
            v.w = (px0 + 3 < nvalid) ? hi.y : NEGV;
            *(float4*)(ob + (size_t)n * Hh * Ww + px0) = v;
        }
        __syncthreads();   // all warps done reading Fs[g&1] before it is refilled
    }
}

extern "C" void kernel_launch(void* const* d_in, const int* in_sizes, int n_in,
                              void* d_out, int out_size) {
    const float* feats   = (const float*)d_in[0];
    const float* kf      = (const float*)d_in[1];
    const float* Wk      = (const float*)d_in[2];
    const float* bk      = (const float*)d_in[3];
    const float* Wf      = (const float*)d_in[4];
    const float* bf      = (const float*)d_in[5];
    const float* db      = (const float*)d_in[6];
    const int*   imshape = (const int*)d_in[7];

    float* logits  = (float*)d_out;
    float* centers = logits + (size_t)Bq * Nn * Hh * Ww;

    prep_kernel<<<Bq * Nn, 128>>>(kf, Wk, bk, Wf, bf, db, centers);
    main_kernel<<<dim3(Ww / TILE, Hh / GROUP, Bq), 128>>>(feats, imshape, logits);
}